// round 2
// baseline (speedup 1.0000x reference)
#include <cuda_runtime.h>
#include <cstdint>
#include <cstddef>

// Problem dims (fixed by the reference)
#define B_SZ    4
#define L_SEQ   4096
#define DMODEL  1024
#define NHEADS  16
#define DHEAD   64
#define M_DIM   (B_SZ * L_SEQ)     // 16384
#define N_DIM   (3 * DMODEL)       // 3072
#define K_DIM   DMODEL             // 1024
#define NSPLIT  8
#define ROWS_PER_SPLIT (L_SEQ / NSPLIT)   // 512
#define SCALE_Q 0.125f             // 64^-0.5

// ---------------- device scratch (no allocations allowed) ----------------
__device__ float g_qkv[(size_t)M_DIM * N_DIM];                 // 201 MB, qkv projection
__device__ float g_ctx_part[(size_t)NSPLIT * 64 * DHEAD * DHEAD]; // 8 MB
__device__ float g_s_part[(size_t)NSPLIT * 64 * DHEAD];          // 128 KB
__device__ float g_ctx[(size_t)64 * DHEAD * DHEAD];              // 1 MB

// ============================================================================
// Kernel 1: qkv = x @ w_qkv^T   (A: [M,K] row-major, B(w): [N,K] row-major)
// Classic 128x128x8 fp32 SGEMM, 256 threads, 8x8 per thread (4+4 split),
// register-prefetch of the next global tile.
// ============================================================================
#define BM 128
#define BN 128
#define BK 8
#define SMP 132   // padded row length to dodge store bank conflicts

__global__ __launch_bounds__(256) void sgemm_qkv(const float* __restrict__ A,
                                                 const float* __restrict__ Bw) {
    __shared__ float sA[BK][SMP];
    __shared__ float sB[BK][SMP];

    const int bx = blockIdx.x;   // N tiles: 24
    const int by = blockIdx.y;   // M tiles: 128
    const int tid = threadIdx.x;

    const int lrow = tid >> 1;          // 0..127
    const int lk   = (tid & 1) * 4;     // 0 or 4

    const float* Aptr = A  + (size_t)(by * BM + lrow) * K_DIM + lk;
    const float* Bptr = Bw + (size_t)(bx * BN + lrow) * K_DIM + lk;

    const int tx = tid & 15;
    const int ty = tid >> 4;

    float acc[8][8];
    #pragma unroll
    for (int i = 0; i < 8; ++i)
        #pragma unroll
        for (int j = 0; j < 8; ++j) acc[i][j] = 0.f;

    float4 a_next = *(const float4*)(Aptr);
    float4 b_next = *(const float4*)(Bptr);

    const int KT = K_DIM / BK;  // 128
    for (int kt = 0; kt < KT; ++kt) {
        sA[lk + 0][lrow] = a_next.x;
        sA[lk + 1][lrow] = a_next.y;
        sA[lk + 2][lrow] = a_next.z;
        sA[lk + 3][lrow] = a_next.w;
        sB[lk + 0][lrow] = b_next.x;
        sB[lk + 1][lrow] = b_next.y;
        sB[lk + 2][lrow] = b_next.z;
        sB[lk + 3][lrow] = b_next.w;
        __syncthreads();

        if (kt + 1 < KT) {
            a_next = *(const float4*)(Aptr + (size_t)(kt + 1) * BK);
            b_next = *(const float4*)(Bptr + (size_t)(kt + 1) * BK);
        }

        #pragma unroll
        for (int kk = 0; kk < BK; ++kk) {
            float ar[8], br[8];
            *(float4*)&ar[0] = *(const float4*)&sA[kk][ty * 4];
            *(float4*)&ar[4] = *(const float4*)&sA[kk][64 + ty * 4];
            *(float4*)&br[0] = *(const float4*)&sB[kk][tx * 4];
            *(float4*)&br[4] = *(const float4*)&sB[kk][64 + tx * 4];
            #pragma unroll
            for (int i = 0; i < 8; ++i)
                #pragma unroll
                for (int j = 0; j < 8; ++j)
                    acc[i][j] += ar[i] * br[j];
        }
        __syncthreads();
    }

    // epilogue: coalesced float4 stores into g_qkv
    #pragma unroll
    for (int i = 0; i < 8; ++i) {
        int m = by * BM + ((i < 4) ? (ty * 4 + i) : (64 + ty * 4 + (i - 4)));
        float* crow = &g_qkv[(size_t)m * N_DIM + bx * BN];
        float4 v0 = make_float4(acc[i][0], acc[i][1], acc[i][2], acc[i][3]);
        float4 v1 = make_float4(acc[i][4], acc[i][5], acc[i][6], acc[i][7]);
        *(float4*)(crow + tx * 4)      = v0;
        *(float4*)(crow + 64 + tx * 4) = v1;
    }
}

// ============================================================================
// Kernel 2: per (b,h,split): partial  s_d = sum_n exp(k[n,d])  (masked rows -> 0)
//                            ctx_raw[d][e] = sum_n exp(k[n,d]) * v[n,e]
// No max-subtraction needed: |k| < ~5 by construction (softmax shift-invariant).
// qkv layout: channel (h*64+d)*3 + {0:q, 1:k, 2:v}
// ============================================================================
#define K2_ROWS 16

__global__ __launch_bounds__(256) void ctx_partial(const int* __restrict__ mask) {
    const int bh    = blockIdx.x;   // 0..63
    const int split = blockIdx.y;   // 0..7
    const int b = bh >> 4, h = bh & 15;
    const int tid = threadIdx.x;

    const int d_own = tid >> 2;          // 0..63
    const int e0    = (tid & 3) << 4;    // 0,16,32,48

    __shared__ float sk[K2_ROWS][64];
    __shared__ float sv[K2_ROWS][64];

    float ctx[16];
    #pragma unroll
    for (int j = 0; j < 16; ++j) ctx[j] = 0.f;
    float ssum = 0.f;

    const int row0 = split * ROWS_PER_SPLIT;
    const float* base = g_qkv + (size_t)b * L_SEQ * N_DIM + h * (DHEAD * 3);
    const int* mrow = mask + b * L_SEQ;

    for (int t0 = 0; t0 < ROWS_PER_SPLIT; t0 += K2_ROWS) {
        // stage K2_ROWS rows of k (as exp) and v
        #pragma unroll
        for (int i = 0; i < 4; ++i) {
            int idx = tid + 256 * i;     // 0..1023
            int r = idx >> 6;
            int d = idx & 63;
            int n = row0 + t0 + r;
            const float* p = base + (size_t)n * N_DIM + d * 3;
            float kv = __ldg(p + 1);
            float vv = __ldg(p + 2);
            int mk = __ldg(mrow + n);
            sk[r][d] = mk ? __expf(kv) : 0.f;
            sv[r][d] = vv;
        }
        __syncthreads();
        #pragma unroll
        for (int r = 0; r < K2_ROWS; ++r) {
            float w = sk[r][d_own];
            ssum += w;
            #pragma unroll
            for (int j = 0; j < 16; ++j)
                ctx[j] += w * sv[r][e0 + j];
        }
        __syncthreads();
    }

    float* cp = g_ctx_part + ((size_t)split * 64 + bh) * (DHEAD * DHEAD);
    #pragma unroll
    for (int j = 0; j < 16; ++j)
        cp[d_own * DHEAD + e0 + j] = ctx[j];
    if ((tid & 3) == 0)
        g_s_part[((size_t)split * 64 + bh) * DHEAD + d_own] = ssum;
}

// ============================================================================
// Kernel 3: combine partials + memory-KV contribution, normalize:
//   ctx[d][e] = (sum_p part + sum_j exp(mem_k[j,d]) * mem_v[j,e]) / (sum_p s + sum_j exp(mem_k[j,d]))
// ============================================================================
__global__ __launch_bounds__(256) void ctx_combine(const float* __restrict__ mem_kv) {
    const int bh = blockIdx.x;     // 0..63
    const int h = bh & 15;
    const int tid = threadIdx.x;
    const int d  = tid >> 2;
    const int e0 = (tid & 3) << 4;

    // mem_k[h][j][d] at mem_kv[(h*4+j)*64 + d]; mem_v offset + 16*4*64
    float wj[4];
    float s = 0.f;
    #pragma unroll
    for (int j = 0; j < 4; ++j) {
        wj[j] = __expf(mem_kv[(h * 4 + j) * 64 + d]);
        s += wj[j];
    }
    #pragma unroll
    for (int p = 0; p < NSPLIT; ++p)
        s += g_s_part[((size_t)p * 64 + bh) * DHEAD + d];
    float inv = 1.f / s;

    const float* mem_v = mem_kv + NHEADS * 4 * DHEAD;
    #pragma unroll
    for (int jj = 0; jj < 16; ++jj) {
        int e = e0 + jj;
        float acc = 0.f;
        #pragma unroll
        for (int j = 0; j < 4; ++j)
            acc += wj[j] * mem_v[(h * 4 + j) * 64 + e];
        #pragma unroll
        for (int p = 0; p < NSPLIT; ++p)
            acc += g_ctx_part[(((size_t)p * 64 + bh) * (DHEAD * DHEAD)) + d * DHEAD + e];
        g_ctx[(size_t)bh * (DHEAD * DHEAD) + d * DHEAD + e] = acc * inv;
    }
}

// ============================================================================
// Kernel 4: out[b,l,h*64+e] = mask * sum_d softmax_d(q*SCALE)[d] * ctx[b,h][d][e]
// One block per (b,h, tile of 128 l-rows); ctx cached in smem; warp per row.
// ============================================================================
__global__ __launch_bounds__(256) void out_kernel(const int* __restrict__ mask,
                                                  float* __restrict__ out) {
    const int bh = blockIdx.x;    // 0..63
    const int lt = blockIdx.y;    // 0..31
    const int b = bh >> 4, h = bh & 15;
    const int tid = threadIdx.x;

    __shared__ float sctx[DHEAD * DHEAD];   // 16 KB
    {
        const float4* src = (const float4*)(g_ctx + (size_t)bh * (DHEAD * DHEAD));
        float4* dst = (float4*)sctx;
        for (int i = tid; i < (DHEAD * DHEAD) / 4; i += 256)
            dst[i] = src[i];
    }
    __syncthreads();

    const int warp = tid >> 5;
    const int lane = tid & 31;

    for (int it = 0; it < 16; ++it) {
        const int l = lt * 128 + it * 8 + warp;
        const int n = b * L_SEQ + l;
        float* orow = out + (size_t)n * DMODEL + h * DHEAD;

        if (mask[n] == 0) {
            orow[lane]      = 0.f;
            orow[lane + 32] = 0.f;
            continue;
        }

        const float* qp = g_qkv + (size_t)n * N_DIM + h * (DHEAD * 3);
        float q0 = __ldg(qp + lane * 3);
        float q1 = __ldg(qp + (lane + 32) * 3);

        // softmax over d (64); |q*SCALE| small -> no max-subtraction needed
        float x0 = __expf(q0 * SCALE_Q);
        float x1 = __expf(q1 * SCALE_Q);
        float s = x0 + x1;
        #pragma unroll
        for (int o = 16; o; o >>= 1)
            s += __shfl_xor_sync(0xffffffff, s, o);
        float inv = 1.f / s;
        float w0 = x0 * inv;
        float w1 = x1 * inv;

        float acc0 = 0.f, acc1 = 0.f;
        #pragma unroll
        for (int dd = 0; dd < 64; ++dd) {
            float qd = __shfl_sync(0xffffffff, (dd < 32) ? w0 : w1, dd & 31);
            acc0 += qd * sctx[dd * DHEAD + lane];
            acc1 += qd * sctx[dd * DHEAD + lane + 32];
        }
        orow[lane]      = acc0;
        orow[lane + 32] = acc1;
    }
}

// ============================================================================
extern "C" void kernel_launch(void* const* d_in, const int* in_sizes, int n_in,
                              void* d_out, int out_size) {
    const float* x      = (const float*)d_in[0];   // (4,4096,1024)
    const float* w_qkv  = (const float*)d_in[1];   // (3072,1024)
    const float* mem_kv = (const float*)d_in[2];   // (2,16,4,64)
    const int*   mask   = (const int*)d_in[3];     // (4,4096)
    float* out = (float*)d_out;

    dim3 g1(N_DIM / BN, M_DIM / BM);               // 24 x 128
    sgemm_qkv<<<g1, 256>>>(x, w_qkv);

    dim3 g2(64, NSPLIT);
    ctx_partial<<<g2, 256>>>(mask);

    ctx_combine<<<64, 256>>>(mem_kv);

    dim3 g3(64, L_SEQ / 128);                      // 64 x 32
    out_kernel<<<g3, 256>>>(mask, out);
}

// round 12
// speedup vs baseline: 1.9401x; 1.9401x over previous
#include <cuda_runtime.h>
#include <cstdint>
#include <cstddef>

// ---------------------------------------------------------------------------
// Problem dims (fixed by the reference)
// ---------------------------------------------------------------------------
#define B_SZ    4
#define L_SEQ   4096
#define DMODEL  1024
#define NHEADS  16
#define DHEAD   64
#define M_DIM   (B_SZ * L_SEQ)     // 16384
#define N_DIM   (3 * DMODEL)       // 3072
#define K_DIM   DMODEL             // 1024
#define NSPLIT  8
#define ROWS_PER_SPLIT (L_SEQ / NSPLIT)   // 512
#define SCALE_Q 0.125f             // 64^-0.5

// ---------------- device scratch (no allocations allowed) ----------------
__device__ float g_qkv[(size_t)M_DIM * N_DIM];                    // 201 MB
__device__ float g_xr [(size_t)M_DIM * K_DIM];                    // 64 MB (tf32-rounded x)
__device__ float g_wr [(size_t)N_DIM * K_DIM];                    // 12 MB (tf32-rounded w)
__device__ float g_ctx_part[(size_t)NSPLIT * 64 * DHEAD * DHEAD]; // 8 MB
__device__ float g_s_part[(size_t)NSPLIT * 64 * DHEAD];           // 128 KB
__device__ float g_ctx[(size_t)64 * DHEAD * DHEAD];               // 1 MB

// ---------------------------------------------------------------------------
// PTX helpers — baseline sm_80+ features ONLY (toolchain targets sm_103,
// arch-specific sm_103a instructions are unavailable).
// ---------------------------------------------------------------------------
__device__ __forceinline__ uint32_t smem_u32(const void* p) {
    uint32_t r;
    asm("{ .reg .u64 t; cvta.to.shared.u64 t, %1; cvt.u32.u64 %0, t; }"
        : "=r"(r) : "l"(p));
    return r;
}

__device__ __forceinline__ void cp_async16(uint32_t dst, const float* src) {
    asm volatile("cp.async.cg.shared.global [%0], [%1], 16;"
                 :: "r"(dst), "l"(src) : "memory");
}
#define CP_COMMIT() asm volatile("cp.async.commit_group;" ::: "memory")
#define CP_WAIT(n)  asm volatile("cp.async.wait_group %0;" :: "n"(n) : "memory")

// m16n8k8 tf32 MMA (baseline PTX, sm_80+)
__device__ __forceinline__ void mma_tf32(float* c, const uint32_t* a, const uint32_t* b) {
    asm volatile(
        "mma.sync.aligned.m16n8k8.row.col.f32.tf32.tf32.f32 "
        "{%0,%1,%2,%3}, {%4,%5,%6,%7}, {%8,%9}, {%0,%1,%2,%3};"
        : "+f"(c[0]), "+f"(c[1]), "+f"(c[2]), "+f"(c[3])
        : "r"(a[0]), "r"(a[1]), "r"(a[2]), "r"(a[3]),
          "r"(b[0]), "r"(b[1]));
}

// ---------------------------------------------------------------------------
// Kernel 0: round f32 -> tf32 (RNA) so the MMA sees round-to-nearest operands
// ---------------------------------------------------------------------------
__global__ __launch_bounds__(256) void round_tf32(const float* __restrict__ in,
                                                  float* __restrict__ out, int n4) {
    int i = blockIdx.x * blockDim.x + threadIdx.x;
    if (i >= n4) return;
    float4 v = ((const float4*)in)[i];
    uint32_t a, b, c, d;
    asm("cvt.rna.tf32.f32 %0, %1;" : "=r"(a) : "f"(v.x));
    asm("cvt.rna.tf32.f32 %0, %1;" : "=r"(b) : "f"(v.y));
    asm("cvt.rna.tf32.f32 %0, %1;" : "=r"(c) : "f"(v.z));
    asm("cvt.rna.tf32.f32 %0, %1;" : "=r"(d) : "f"(v.w));
    float4 o;
    o.x = __uint_as_float(a); o.y = __uint_as_float(b);
    o.z = __uint_as_float(c); o.w = __uint_as_float(d);
    ((float4*)out)[i] = o;
}

// ---------------------------------------------------------------------------
// Kernel 1: qkv = x @ w^T — tf32 mma.sync GEMM
//   128x128x32 CTA tile, 256 threads = 8 warps (2x4), 64x32 warp tile,
//   3-stage cp.async pipeline, XOR-swizzled SMEM (conflict-free both ways).
//   A: [M,K] row-major.  B(w): [N,K] row-major (so B^T is col-major -> .col).
// ---------------------------------------------------------------------------
#define BM 128
#define BN 128
#define BKG 32
#define GSTAGES 3
#define STAGE_FLOATS (BM * BKG)            // 4096 floats = 16 KB per matrix
#define SLOT_FLOATS  (2 * STAGE_FLOATS)    // A + B
#define GEMM_SMEM    (GSTAGES * SLOT_FLOATS * 4)   // 98304 B

// swizzled float index for element (row, k) inside a [128][32] tile
__device__ __forceinline__ int smidx(int row, int k) {
    return row * BKG + ((((unsigned)k >> 2) ^ (row & 7)) << 2) + (k & 3);
}

__global__ __launch_bounds__(256) void gemm_mma(const float* __restrict__ A,
                                                const float* __restrict__ Bw) {
    extern __shared__ float smem[];
    const uint32_t sb = smem_u32(smem);
    const int tid  = threadIdx.x;
    const int lane = tid & 31;
    const int wid  = tid >> 5;
    const int wm   = wid >> 2;           // 0..1
    const int wn   = wid & 3;            // 0..3

    const int m0 = blockIdx.y * BM;
    const int n0 = blockIdx.x * BN;
    const float* Ab = A  + (size_t)m0 * K_DIM;
    const float* Bb = Bw + (size_t)n0 * K_DIM;

    float acc[4][4][4];
    #pragma unroll
    for (int i = 0; i < 4; ++i)
        #pragma unroll
        for (int j = 0; j < 4; ++j)
            #pragma unroll
            for (int q = 0; q < 4; ++q) acc[i][j][q] = 0.f;

    // ---- stage loader: 4 A-chunks + 4 B-chunks of 16B per thread ----
    auto load_stage = [&](int s, int slot) {
        const uint32_t dA = sb + (uint32_t)slot * (SLOT_FLOATS * 4);
        const uint32_t dB = dA + STAGE_FLOATS * 4;
        const float* ga = Ab + s * BKG;
        const float* gb = Bb + s * BKG;
        #pragma unroll
        for (int i = 0; i < 4; ++i) {
            const int chunk = i * 256 + tid;      // 0..1023
            const int row   = chunk >> 3;         // 0..127
            const int c8    = chunk & 7;          // 16B chunk within row
            const int csw   = c8 ^ (row & 7);
            const uint32_t so = (uint32_t)(row * BKG + csw * 4) * 4;
            const size_t   go = (size_t)row * K_DIM + c8 * 4;
            cp_async16(dA + so, ga + go);
            cp_async16(dB + so, gb + go);
        }
        CP_COMMIT();
    };

    // prologue: 2 stages in flight
    load_stage(0, 0);
    load_stage(1, 1);

    const int KS = K_DIM / BKG;   // 32
    const int kl = lane & 3;      // k lane within fragment
    const int gl = lane >> 2;     // group (row/col) lane

    for (int s = 0; s < KS; ++s) {
        const int slot = s % GSTAGES;
        if (s < KS - 1) CP_WAIT(1); else CP_WAIT(0);
        __syncthreads();

        // prefetch s+2 into the slot freed at iteration s-1
        if (s + 2 < KS) load_stage(s + 2, (s + 2) % GSTAGES);

        const float* sA = smem + slot * SLOT_FLOATS;
        const float* sB = sA + STAGE_FLOATS;

        #pragma unroll
        for (int ks = 0; ks < BKG / 8; ++ks) {        // 4 k-steps of 8
            const int k0 = ks * 8 + kl;
            uint32_t afr[4][4], bfr[4][2];
            #pragma unroll
            for (int mt = 0; mt < 4; ++mt) {
                const int r = wm * 64 + mt * 16 + gl;
                afr[mt][0] = __float_as_uint(sA[smidx(r,     k0)]);
                afr[mt][1] = __float_as_uint(sA[smidx(r + 8, k0)]);
                afr[mt][2] = __float_as_uint(sA[smidx(r,     k0 + 4)]);
                afr[mt][3] = __float_as_uint(sA[smidx(r + 8, k0 + 4)]);
            }
            #pragma unroll
            for (int nt = 0; nt < 4; ++nt) {
                const int rn = wn * 32 + nt * 8 + gl;
                bfr[nt][0] = __float_as_uint(sB[smidx(rn, k0)]);
                bfr[nt][1] = __float_as_uint(sB[smidx(rn, k0 + 4)]);
            }
            #pragma unroll
            for (int mt = 0; mt < 4; ++mt)
                #pragma unroll
                for (int nt = 0; nt < 4; ++nt)
                    mma_tf32(acc[mt][nt], afr[mt], bfr[nt]);
        }
        __syncthreads();
    }

    // ---- epilogue: fragment -> g_qkv (float2 stores) ----
    #pragma unroll
    for (int mt = 0; mt < 4; ++mt) {
        const int r = m0 + wm * 64 + mt * 16 + gl;
        #pragma unroll
        for (int nt = 0; nt < 4; ++nt) {
            const int cc = n0 + wn * 32 + nt * 8 + kl * 2;
            float2 v0 = make_float2(acc[mt][nt][0], acc[mt][nt][1]);
            float2 v1 = make_float2(acc[mt][nt][2], acc[mt][nt][3]);
            *(float2*)(g_qkv + (size_t)r       * N_DIM + cc) = v0;
            *(float2*)(g_qkv + (size_t)(r + 8) * N_DIM + cc) = v1;
        }
    }
}

// ============================================================================
// Kernel 2: per (b,h,split): s_d = sum_n exp(k[n,d]); ctx_raw = exp(k)^T v
// ============================================================================
#define K2_ROWS 16

__global__ __launch_bounds__(256) void ctx_partial(const int* __restrict__ mask) {
    const int bh    = blockIdx.x;   // 0..63
    const int split = blockIdx.y;   // 0..7
    const int b = bh >> 4, h = bh & 15;
    const int tid = threadIdx.x;

    const int d_own = tid >> 2;          // 0..63
    const int e0    = (tid & 3) << 4;    // 0,16,32,48

    __shared__ float sk[K2_ROWS][64];
    __shared__ float sv[K2_ROWS][64];

    float ctx[16];
    #pragma unroll
    for (int j = 0; j < 16; ++j) ctx[j] = 0.f;
    float ssum = 0.f;

    const int row0 = split * ROWS_PER_SPLIT;
    const float* base = g_qkv + (size_t)b * L_SEQ * N_DIM + h * (DHEAD * 3);
    const int* mrow = mask + b * L_SEQ;

    for (int t0 = 0; t0 < ROWS_PER_SPLIT; t0 += K2_ROWS) {
        #pragma unroll
        for (int i = 0; i < 4; ++i) {
            int idx = tid + 256 * i;
            int r = idx >> 6;
            int d = idx & 63;
            int n = row0 + t0 + r;
            const float* p = base + (size_t)n * N_DIM + d * 3;
            float kv = __ldg(p + 1);
            float vv = __ldg(p + 2);
            int mk = __ldg(mrow + n);
            sk[r][d] = mk ? __expf(kv) : 0.f;
            sv[r][d] = vv;
        }
        __syncthreads();
        #pragma unroll
        for (int r = 0; r < K2_ROWS; ++r) {
            float w = sk[r][d_own];
            ssum += w;
            #pragma unroll
            for (int j = 0; j < 16; ++j)
                ctx[j] += w * sv[r][e0 + j];
        }
        __syncthreads();
    }

    float* cp = g_ctx_part + ((size_t)split * 64 + bh) * (DHEAD * DHEAD);
    #pragma unroll
    for (int j = 0; j < 16; ++j)
        cp[d_own * DHEAD + e0 + j] = ctx[j];
    if ((tid & 3) == 0)
        g_s_part[((size_t)split * 64 + bh) * DHEAD + d_own] = ssum;
}

// ============================================================================
// Kernel 3: combine partials + memory-KV, normalize
// ============================================================================
__global__ __launch_bounds__(256) void ctx_combine(const float* __restrict__ mem_kv) {
    const int bh = blockIdx.x;     // 0..63
    const int h = bh & 15;
    const int tid = threadIdx.x;
    const int d  = tid >> 2;
    const int e0 = (tid & 3) << 4;

    float wj[4];
    float s = 0.f;
    #pragma unroll
    for (int j = 0; j < 4; ++j) {
        wj[j] = __expf(mem_kv[(h * 4 + j) * 64 + d]);
        s += wj[j];
    }
    #pragma unroll
    for (int p = 0; p < NSPLIT; ++p)
        s += g_s_part[((size_t)p * 64 + bh) * DHEAD + d];
    float inv = 1.f / s;

    const float* mem_v = mem_kv + NHEADS * 4 * DHEAD;
    #pragma unroll
    for (int jj = 0; jj < 16; ++jj) {
        int e = e0 + jj;
        float acc = 0.f;
        #pragma unroll
        for (int j = 0; j < 4; ++j)
            acc += wj[j] * mem_v[(h * 4 + j) * 64 + e];
        #pragma unroll
        for (int p = 0; p < NSPLIT; ++p)
            acc += g_ctx_part[(((size_t)p * 64 + bh) * (DHEAD * DHEAD)) + d * DHEAD + e];
        g_ctx[(size_t)bh * (DHEAD * DHEAD) + d * DHEAD + e] = acc * inv;
    }
}

// ============================================================================
// Kernel 4: out = mask * softmax_d(q*SCALE) @ ctx
// ============================================================================
__global__ __launch_bounds__(256) void out_kernel(const int* __restrict__ mask,
                                                  float* __restrict__ out) {
    const int bh = blockIdx.x;    // 0..63
    const int lt = blockIdx.y;    // 0..31
    const int b = bh >> 4, h = bh & 15;
    const int tid = threadIdx.x;

    __shared__ float sctx[DHEAD * DHEAD];
    {
        const float4* src = (const float4*)(g_ctx + (size_t)bh * (DHEAD * DHEAD));
        float4* dst = (float4*)sctx;
        for (int i = tid; i < (DHEAD * DHEAD) / 4; i += 256)
            dst[i] = src[i];
    }
    __syncthreads();

    const int warp = tid >> 5;
    const int lane = tid & 31;

    for (int it = 0; it < 16; ++it) {
        const int l = lt * 128 + it * 8 + warp;
        const int n = b * L_SEQ + l;
        float* orow = out + (size_t)n * DMODEL + h * DHEAD;

        if (mask[n] == 0) {
            orow[lane]      = 0.f;
            orow[lane + 32] = 0.f;
            continue;
        }

        const float* qp = g_qkv + (size_t)n * N_DIM + h * (DHEAD * 3);
        float q0 = __ldg(qp + lane * 3);
        float q1 = __ldg(qp + (lane + 32) * 3);

        float x0 = __expf(q0 * SCALE_Q);
        float x1 = __expf(q1 * SCALE_Q);
        float s = x0 + x1;
        #pragma unroll
        for (int o = 16; o; o >>= 1)
            s += __shfl_xor_sync(0xffffffff, s, o);
        float inv = 1.f / s;
        float w0 = x0 * inv;
        float w1 = x1 * inv;

        float acc0 = 0.f, acc1 = 0.f;
        #pragma unroll
        for (int dd = 0; dd < 64; ++dd) {
            float qd = __shfl_sync(0xffffffff, (dd < 32) ? w0 : w1, dd & 31);
            acc0 += qd * sctx[dd * DHEAD + lane];
            acc1 += qd * sctx[dd * DHEAD + lane + 32];
        }
        orow[lane]      = acc0;
        orow[lane + 32] = acc1;
    }
}

// ============================================================================
extern "C" void kernel_launch(void* const* d_in, const int* in_sizes, int n_in,
                              void* d_out, int out_size) {
    const float* x      = (const float*)d_in[0];   // (4,4096,1024)
    const float* w_qkv  = (const float*)d_in[1];   // (3072,1024)
    const float* mem_kv = (const float*)d_in[2];   // (2,16,4,64)
    const int*   mask   = (const int*)d_in[3];     // (4,4096)
    float* out = (float*)d_out;

    cudaFuncSetAttribute(gemm_mma, cudaFuncAttributeMaxDynamicSharedMemorySize,
                         GEMM_SMEM);

    float* xr;  cudaGetSymbolAddress((void**)&xr, g_xr);
    float* wr;  cudaGetSymbolAddress((void**)&wr, g_wr);

    round_tf32<<<(M_DIM * K_DIM / 4 + 255) / 256, 256>>>(x, xr, M_DIM * K_DIM / 4);
    round_tf32<<<(N_DIM * K_DIM / 4 + 255) / 256, 256>>>(w_qkv, wr, N_DIM * K_DIM / 4);

    dim3 g1(N_DIM / BN, M_DIM / BM);               // 24 x 128 (N inner -> B stays in L2)
    gemm_mma<<<g1, 256, GEMM_SMEM>>>(xr, wr);

    dim3 g2(64, NSPLIT);
    ctx_partial<<<g2, 256>>>(mask);

    ctx_combine<<<64, 256>>>(mem_kv);

    dim3 g3(64, L_SEQ / 128);                      // 64 x 32
    out_kernel<<<g3, 256>>>(mask, out);
}